// round 1
// baseline (speedup 1.0000x reference)
#include <cuda_runtime.h>
#include <math.h>

// Problem constants
#define SDIM 2048   // state_space
#define HDIM 2048   // hidden_size
#define LNUM 2      // num_layers
#define ANUM 16     // autoregressive steps

// Persistent scratch (allowed: __device__ globals, no runtime allocation)
__device__ float g_hbuf[2][LNUM][HDIM];  // double-buffered hidden state
__device__ float g_c[LNUM][HDIM];        // cell state (in-place safe)
__device__ float g_x[SDIM];              // fed-back input (softmax of prev step)
__device__ float g_logits[SDIM];

__device__ __forceinline__ float sigmoidf_(float x) {
    return 1.0f / (1.0f + __expf(-x));
}

// ---------------------------------------------------------------------------
// LSTM gates + state update for one layer, one timestep.
// One warp computes one (unit, gate) pair: two dot products of length HDIM.
// Block = 512 threads = 16 warps = 4 units. Grid = HDIM/4 = 512 blocks.
// inp and hin are staged in shared memory (float4, conflict-free LDS.128).
// ---------------------------------------------------------------------------
__global__ void __launch_bounds__(512) lstm_gates_kernel(
    const float* __restrict__ Wih,   // [4H, H] for this layer
    const float* __restrict__ Whh,   // [4H, H]
    const float* __restrict__ bih,   // [4H]
    const float* __restrict__ bhh,   // [4H]
    const float* __restrict__ inp,   // [H] layer input
    const float* __restrict__ hin,   // [H] previous hidden (read-only buffer)
    float* __restrict__ hout,        // [H] new hidden (other buffer)
    float* __restrict__ cio)         // [H] cell state, updated in place
{
    __shared__ float4 s_in[HDIM / 4];
    __shared__ float4 s_h[HDIM / 4];
    __shared__ float s_g[4][4];      // [unit_local][gate]

    const int t = threadIdx.x;
    for (int i = t; i < HDIM / 4; i += 512) {
        s_in[i] = ((const float4*)inp)[i];
        s_h[i]  = ((const float4*)hin)[i];
    }
    __syncthreads();

    const int warp   = t >> 5;
    const int lane   = t & 31;
    const int ulocal = warp >> 2;     // 0..3
    const int gate   = warp & 3;      // 0..3 (i, f, g, o)
    const int unit   = blockIdx.x * 4 + ulocal;
    const int row    = gate * HDIM + unit;

    const float4* __restrict__ wi = (const float4*)(Wih + (size_t)row * HDIM);
    const float4* __restrict__ wh = (const float4*)(Whh + (size_t)row * HDIM);

    float acc = 0.0f;
    #pragma unroll
    for (int k = 0; k < 16; k++) {
        float4 a = wi[lane + k * 32];
        float4 b = s_in[lane + k * 32];
        acc = fmaf(a.x, b.x, acc);
        acc = fmaf(a.y, b.y, acc);
        acc = fmaf(a.z, b.z, acc);
        acc = fmaf(a.w, b.w, acc);
    }
    #pragma unroll
    for (int k = 0; k < 16; k++) {
        float4 a = wh[lane + k * 32];
        float4 b = s_h[lane + k * 32];
        acc = fmaf(a.x, b.x, acc);
        acc = fmaf(a.y, b.y, acc);
        acc = fmaf(a.z, b.z, acc);
        acc = fmaf(a.w, b.w, acc);
    }
    #pragma unroll
    for (int o = 16; o > 0; o >>= 1)
        acc += __shfl_xor_sync(0xffffffffu, acc, o);

    if (lane == 0)
        s_g[ulocal][gate] = acc + bih[row] + bhh[row];
    __syncthreads();

    if (t < 4) {
        const int u = blockIdx.x * 4 + t;
        float iv = sigmoidf_(s_g[t][0]);
        float fv = sigmoidf_(s_g[t][1]);
        float gv = tanhf(s_g[t][2]);
        float ov = sigmoidf_(s_g[t][3]);
        float cn = fv * cio[u] + iv * gv;
        cio[u]  = cn;
        hout[u] = ov * tanhf(cn);
    }
}

// ---------------------------------------------------------------------------
// logits = W_out @ h + b_out. One warp per output row.
// Block = 512 threads = 16 rows. Grid = SDIM/16 = 128 blocks.
// ---------------------------------------------------------------------------
__global__ void __launch_bounds__(512) logits_kernel(
    const float* __restrict__ Wout,  // [S, H]
    const float* __restrict__ bout,  // [S]
    const float* __restrict__ h,     // [H]
    float* __restrict__ logits)      // [S]
{
    __shared__ float4 s_h[HDIM / 4];
    const int t = threadIdx.x;
    for (int i = t; i < HDIM / 4; i += 512)
        s_h[i] = ((const float4*)h)[i];
    __syncthreads();

    const int warp = t >> 5;
    const int lane = t & 31;
    const int row  = blockIdx.x * 16 + warp;

    const float4* __restrict__ w = (const float4*)(Wout + (size_t)row * HDIM);
    float acc = 0.0f;
    #pragma unroll
    for (int k = 0; k < 16; k++) {
        float4 a = w[lane + k * 32];
        float4 b = s_h[lane + k * 32];
        acc = fmaf(a.x, b.x, acc);
        acc = fmaf(a.y, b.y, acc);
        acc = fmaf(a.z, b.z, acc);
        acc = fmaf(a.w, b.w, acc);
    }
    #pragma unroll
    for (int o = 16; o > 0; o >>= 1)
        acc += __shfl_xor_sync(0xffffffffu, acc, o);

    if (lane == 0)
        logits[row] = acc + bout[row];
}

// ---------------------------------------------------------------------------
// Softmax over 2048 logits. Single block, 1024 threads (2 elems/thread).
// Writes both the output row for this step and the fed-back input g_x.
// ---------------------------------------------------------------------------
__global__ void __launch_bounds__(1024) softmax_kernel(
    const float* __restrict__ logits,
    float* __restrict__ out_row,     // d_out + step*S
    float* __restrict__ xnext)       // g_x
{
    __shared__ float red[32];
    __shared__ float s_bcast;

    const int t    = threadIdx.x;
    const int warp = t >> 5;
    const int lane = t & 31;

    float a = logits[t];
    float b = logits[t + 1024];

    // --- block max ---
    float m = fmaxf(a, b);
    #pragma unroll
    for (int o = 16; o > 0; o >>= 1)
        m = fmaxf(m, __shfl_xor_sync(0xffffffffu, m, o));
    if (lane == 0) red[warp] = m;
    __syncthreads();
    if (warp == 0) {
        float v = red[lane];
        #pragma unroll
        for (int o = 16; o > 0; o >>= 1)
            v = fmaxf(v, __shfl_xor_sync(0xffffffffu, v, o));
        if (lane == 0) s_bcast = v;
    }
    __syncthreads();
    const float M = s_bcast;

    // --- exp + block sum ---
    float ea = __expf(a - M);
    float eb = __expf(b - M);
    float s = ea + eb;
    #pragma unroll
    for (int o = 16; o > 0; o >>= 1)
        s += __shfl_xor_sync(0xffffffffu, s, o);
    __syncthreads();   // protect red[] reuse
    if (lane == 0) red[warp] = s;
    __syncthreads();
    if (warp == 0) {
        float v = red[lane];
        #pragma unroll
        for (int o = 16; o > 0; o >>= 1)
            v += __shfl_xor_sync(0xffffffffu, v, o);
        if (lane == 0) s_bcast = v;
    }
    __syncthreads();
    const float inv = 1.0f / s_bcast;

    float pa = ea * inv;
    float pb = eb * inv;
    out_row[t]        = pa;
    out_row[t + 1024] = pb;
    xnext[t]          = pa;
    xnext[t + 1024]   = pb;
}

// ---------------------------------------------------------------------------
// kernel_launch: 2 memset nodes + 64 kernel nodes, all graph-capturable.
// ---------------------------------------------------------------------------
extern "C" void kernel_launch(void* const* d_in, const int* in_sizes, int n_in,
                              void* d_out, int out_size)
{
    const float* x    = (const float*)d_in[0];
    const float* Wih  = (const float*)d_in[1];   // [L, 4H, H]
    const float* Whh  = (const float*)d_in[2];   // [L, 4H, H]
    const float* bih  = (const float*)d_in[3];   // [L, 4H]
    const float* bhh  = (const float*)d_in[4];   // [L, 4H]
    const float* Wout = (const float*)d_in[5];   // [S, H]
    const float* bout = (const float*)d_in[6];   // [S]
    float* out = (float*)d_out;                  // [A, S]

    float *hbuf, *cbuf, *gx, *gl;
    cudaGetSymbolAddress((void**)&hbuf, g_hbuf);
    cudaGetSymbolAddress((void**)&cbuf, g_c);
    cudaGetSymbolAddress((void**)&gx,   g_x);
    cudaGetSymbolAddress((void**)&gl,   g_logits);

    cudaMemsetAsync(hbuf, 0, sizeof(float) * 2 * LNUM * HDIM);
    cudaMemsetAsync(cbuf, 0, sizeof(float) * LNUM * HDIM);

    const size_t wOffL = (size_t)4 * HDIM * HDIM;  // per-layer weight stride
    const size_t bOffL = (size_t)4 * HDIM;         // per-layer bias stride

    for (int step = 0; step < ANUM; step++) {
        const int p = step & 1;
        const float* inp0 = (step == 0) ? x : gx;

        float* h0_in  = hbuf + ((size_t)p       * LNUM + 0) * HDIM;
        float* h0_out = hbuf + ((size_t)(1 - p) * LNUM + 0) * HDIM;
        float* h1_in  = hbuf + ((size_t)p       * LNUM + 1) * HDIM;
        float* h1_out = hbuf + ((size_t)(1 - p) * LNUM + 1) * HDIM;

        // layer 0
        lstm_gates_kernel<<<HDIM / 4, 512>>>(
            Wih, Whh, bih, bhh, inp0, h0_in, h0_out, cbuf);
        // layer 1
        lstm_gates_kernel<<<HDIM / 4, 512>>>(
            Wih + wOffL, Whh + wOffL, bih + bOffL, bhh + bOffL,
            h0_out, h1_in, h1_out, cbuf + HDIM);
        // output projection
        logits_kernel<<<SDIM / 16, 512>>>(Wout, bout, h1_out, gl);
        // softmax + feedback + output write
        softmax_kernel<<<1, 1024>>>(gl, out + (size_t)step * SDIM, gx);
    }
}

// round 2
// speedup vs baseline: 1.1789x; 1.1789x over previous
#include <cuda_runtime.h>
#include <cuda_fp16.h>
#include <math.h>

// Problem constants
#define SDIM 2048   // state_space
#define HDIM 2048   // hidden_size
#define LNUM 2      // num_layers
#define ANUM 16     // autoregressive steps

// Persistent scratch (__device__ globals only — no runtime allocation)
__device__ float g_hbuf[2][LNUM][HDIM];  // double-buffered hidden state
__device__ float g_c[LNUM][HDIM];        // cell state (in-place safe)
__device__ float g_x[SDIM];              // fed-back input (softmax of prev step)
__device__ float g_logits[SDIM];

// fp16 weight caches, rebuilt every launch (determinism rule forbids caching)
__device__ __half g_wih16[LNUM * 4 * HDIM * HDIM];  // 67 MB
__device__ __half g_whh16[LNUM * 4 * HDIM * HDIM];  // 67 MB
__device__ __half g_wout16[SDIM * HDIM];            // 8.4 MB

__device__ __forceinline__ float sigmoidf_(float x) {
    return 1.0f / (1.0f + __expf(-x));
}

// ---------------------------------------------------------------------------
// fp32 -> fp16 conversion, 8 elements per thread per iter (vectorized).
// n must be a multiple of 8 (true for all our arrays).
// ---------------------------------------------------------------------------
__global__ void __launch_bounds__(256) cvt_f32_to_f16_kernel(
    const float* __restrict__ src, __half* __restrict__ dst, int n)
{
    int i = (blockIdx.x * blockDim.x + threadIdx.x) * 8;
    const int stride = gridDim.x * blockDim.x * 8;
    for (; i < n; i += stride) {
        float4 a = *(const float4*)(src + i);
        float4 b = *(const float4*)(src + i + 4);
        __half2 h0 = __floats2half2_rn(a.x, a.y);
        __half2 h1 = __floats2half2_rn(a.z, a.w);
        __half2 h2 = __floats2half2_rn(b.x, b.y);
        __half2 h3 = __floats2half2_rn(b.z, b.w);
        uint4 o;
        o.x = *(unsigned*)&h0;
        o.y = *(unsigned*)&h1;
        o.z = *(unsigned*)&h2;
        o.w = *(unsigned*)&h3;
        *(uint4*)(dst + i) = o;
    }
}

// ---------------------------------------------------------------------------
// LSTM gates + state update, fp16 weights / fp32 activations+accumulate.
// One warp per (unit, gate): two dot products of length HDIM.
// Block = 512 threads = 16 warps = 4 units. Grid = HDIM/4 = 512 blocks.
// ---------------------------------------------------------------------------
__global__ void __launch_bounds__(512) lstm_gates_kernel(
    const __half* __restrict__ Wih,  // [4H, H] fp16, this layer
    const __half* __restrict__ Whh,  // [4H, H] fp16
    const float* __restrict__ bih,   // [4H] fp32
    const float* __restrict__ bhh,   // [4H]
    const float* __restrict__ inp,   // [H]
    const float* __restrict__ hin,   // [H]
    float* __restrict__ hout,        // [H]
    float* __restrict__ cio)         // [H] in-place
{
    __shared__ float4 s_in[HDIM / 4];
    __shared__ float4 s_h[HDIM / 4];
    __shared__ float s_g[4][4];

    const int t = threadIdx.x;
    for (int i = t; i < HDIM / 4; i += 512) {
        s_in[i] = ((const float4*)inp)[i];
        s_h[i]  = ((const float4*)hin)[i];
    }
    __syncthreads();

    const int warp   = t >> 5;
    const int lane   = t & 31;
    const int ulocal = warp >> 2;
    const int gate   = warp & 3;
    const int unit   = blockIdx.x * 4 + ulocal;
    const int row    = gate * HDIM + unit;

    const uint4* __restrict__ wi4 = (const uint4*)(Wih + (size_t)row * HDIM);
    const uint4* __restrict__ wh4 = (const uint4*)(Whh + (size_t)row * HDIM);

    float acc = 0.0f;
    // 2048 halfs per row, 8 halfs (one uint4) per lane per iter -> 8 iters
    #pragma unroll
    for (int k = 0; k < 8; k++) {
        uint4 wv = wi4[lane + k * 32];
        const __half2* hp = reinterpret_cast<const __half2*>(&wv);
        float4 b0 = s_in[2 * (lane + k * 32)];
        float4 b1 = s_in[2 * (lane + k * 32) + 1];
        float2 f0 = __half22float2(hp[0]);
        float2 f1 = __half22float2(hp[1]);
        float2 f2 = __half22float2(hp[2]);
        float2 f3 = __half22float2(hp[3]);
        acc = fmaf(f0.x, b0.x, acc); acc = fmaf(f0.y, b0.y, acc);
        acc = fmaf(f1.x, b0.z, acc); acc = fmaf(f1.y, b0.w, acc);
        acc = fmaf(f2.x, b1.x, acc); acc = fmaf(f2.y, b1.y, acc);
        acc = fmaf(f3.x, b1.z, acc); acc = fmaf(f3.y, b1.w, acc);
    }
    #pragma unroll
    for (int k = 0; k < 8; k++) {
        uint4 wv = wh4[lane + k * 32];
        const __half2* hp = reinterpret_cast<const __half2*>(&wv);
        float4 b0 = s_h[2 * (lane + k * 32)];
        float4 b1 = s_h[2 * (lane + k * 32) + 1];
        float2 f0 = __half22float2(hp[0]);
        float2 f1 = __half22float2(hp[1]);
        float2 f2 = __half22float2(hp[2]);
        float2 f3 = __half22float2(hp[3]);
        acc = fmaf(f0.x, b0.x, acc); acc = fmaf(f0.y, b0.y, acc);
        acc = fmaf(f1.x, b0.z, acc); acc = fmaf(f1.y, b0.w, acc);
        acc = fmaf(f2.x, b1.x, acc); acc = fmaf(f2.y, b1.y, acc);
        acc = fmaf(f3.x, b1.z, acc); acc = fmaf(f3.y, b1.w, acc);
    }
    #pragma unroll
    for (int o = 16; o > 0; o >>= 1)
        acc += __shfl_xor_sync(0xffffffffu, acc, o);

    if (lane == 0)
        s_g[ulocal][gate] = acc + bih[row] + bhh[row];
    __syncthreads();

    if (t < 4) {
        const int u = blockIdx.x * 4 + t;
        float iv = sigmoidf_(s_g[t][0]);
        float fv = sigmoidf_(s_g[t][1]);
        float gv = tanhf(s_g[t][2]);
        float ov = sigmoidf_(s_g[t][3]);
        float cn = fv * cio[u] + iv * gv;
        cio[u]  = cn;
        hout[u] = ov * tanhf(cn);
    }
}

// ---------------------------------------------------------------------------
// logits = W_out(fp16) @ h + b_out. One warp per row.
// Block = 512 = 16 rows. Grid = SDIM/16 = 128 blocks.
// ---------------------------------------------------------------------------
__global__ void __launch_bounds__(512) logits_kernel(
    const __half* __restrict__ Wout,
    const float* __restrict__ bout,
    const float* __restrict__ h,
    float* __restrict__ logits)
{
    __shared__ float4 s_h[HDIM / 4];
    const int t = threadIdx.x;
    for (int i = t; i < HDIM / 4; i += 512)
        s_h[i] = ((const float4*)h)[i];
    __syncthreads();

    const int warp = t >> 5;
    const int lane = t & 31;
    const int row  = blockIdx.x * 16 + warp;

    const uint4* __restrict__ w4 = (const uint4*)(Wout + (size_t)row * HDIM);
    float acc = 0.0f;
    #pragma unroll
    for (int k = 0; k < 8; k++) {
        uint4 wv = w4[lane + k * 32];
        const __half2* hp = reinterpret_cast<const __half2*>(&wv);
        float4 b0 = s_h[2 * (lane + k * 32)];
        float4 b1 = s_h[2 * (lane + k * 32) + 1];
        float2 f0 = __half22float2(hp[0]);
        float2 f1 = __half22float2(hp[1]);
        float2 f2 = __half22float2(hp[2]);
        float2 f3 = __half22float2(hp[3]);
        acc = fmaf(f0.x, b0.x, acc); acc = fmaf(f0.y, b0.y, acc);
        acc = fmaf(f1.x, b0.z, acc); acc = fmaf(f1.y, b0.w, acc);
        acc = fmaf(f2.x, b1.x, acc); acc = fmaf(f2.y, b1.y, acc);
        acc = fmaf(f3.x, b1.z, acc); acc = fmaf(f3.y, b1.w, acc);
    }
    #pragma unroll
    for (int o = 16; o > 0; o >>= 1)
        acc += __shfl_xor_sync(0xffffffffu, acc, o);

    if (lane == 0)
        logits[row] = acc + bout[row];
}

// ---------------------------------------------------------------------------
// Softmax over 2048 logits (unchanged from R1).
// ---------------------------------------------------------------------------
__global__ void __launch_bounds__(1024) softmax_kernel(
    const float* __restrict__ logits,
    float* __restrict__ out_row,
    float* __restrict__ xnext)
{
    __shared__ float red[32];
    __shared__ float s_bcast;

    const int t    = threadIdx.x;
    const int warp = t >> 5;
    const int lane = t & 31;

    float a = logits[t];
    float b = logits[t + 1024];

    float m = fmaxf(a, b);
    #pragma unroll
    for (int o = 16; o > 0; o >>= 1)
        m = fmaxf(m, __shfl_xor_sync(0xffffffffu, m, o));
    if (lane == 0) red[warp] = m;
    __syncthreads();
    if (warp == 0) {
        float v = red[lane];
        #pragma unroll
        for (int o = 16; o > 0; o >>= 1)
            v = fmaxf(v, __shfl_xor_sync(0xffffffffu, v, o));
        if (lane == 0) s_bcast = v;
    }
    __syncthreads();
    const float M = s_bcast;

    float ea = __expf(a - M);
    float eb = __expf(b - M);
    float s = ea + eb;
    #pragma unroll
    for (int o = 16; o > 0; o >>= 1)
        s += __shfl_xor_sync(0xffffffffu, s, o);
    __syncthreads();
    if (lane == 0) red[warp] = s;
    __syncthreads();
    if (warp == 0) {
        float v = red[lane];
        #pragma unroll
        for (int o = 16; o > 0; o >>= 1)
            v += __shfl_xor_sync(0xffffffffu, v, o);
        if (lane == 0) s_bcast = v;
    }
    __syncthreads();
    const float inv = 1.0f / s_bcast;

    float pa = ea * inv;
    float pb = eb * inv;
    out_row[t]        = pa;
    out_row[t + 1024] = pb;
    xnext[t]          = pa;
    xnext[t + 1024]   = pb;
}

// ---------------------------------------------------------------------------
// kernel_launch
// ---------------------------------------------------------------------------
extern "C" void kernel_launch(void* const* d_in, const int* in_sizes, int n_in,
                              void* d_out, int out_size)
{
    const float* x    = (const float*)d_in[0];
    const float* Wih  = (const float*)d_in[1];   // [L, 4H, H]
    const float* Whh  = (const float*)d_in[2];   // [L, 4H, H]
    const float* bih  = (const float*)d_in[3];   // [L, 4H]
    const float* bhh  = (const float*)d_in[4];   // [L, 4H]
    const float* Wout = (const float*)d_in[5];   // [S, H]
    const float* bout = (const float*)d_in[6];   // [S]
    float* out = (float*)d_out;                  // [A, S]

    float *hbuf, *cbuf, *gx, *gl;
    __half *wih16, *whh16, *wout16;
    cudaGetSymbolAddress((void**)&hbuf,   g_hbuf);
    cudaGetSymbolAddress((void**)&cbuf,   g_c);
    cudaGetSymbolAddress((void**)&gx,     g_x);
    cudaGetSymbolAddress((void**)&gl,     g_logits);
    cudaGetSymbolAddress((void**)&wih16,  g_wih16);
    cudaGetSymbolAddress((void**)&whh16,  g_whh16);
    cudaGetSymbolAddress((void**)&wout16, g_wout16);

    cudaMemsetAsync(hbuf, 0, sizeof(float) * 2 * LNUM * HDIM);
    cudaMemsetAsync(cbuf, 0, sizeof(float) * LNUM * HDIM);

    // Weight conversion (every launch; caching across calls is forbidden)
    const int nW = LNUM * 4 * HDIM * HDIM;   // 33.5M
    const int nO = SDIM * HDIM;              // 4.2M
    cvt_f32_to_f16_kernel<<<2048, 256>>>(Wih,  wih16,  nW);
    cvt_f32_to_f16_kernel<<<2048, 256>>>(Whh,  whh16,  nW);
    cvt_f32_to_f16_kernel<<<512,  256>>>(Wout, wout16, nO);

    const size_t wOffL = (size_t)4 * HDIM * HDIM;
    const size_t bOffL = (size_t)4 * HDIM;

    for (int step = 0; step < ANUM; step++) {
        const int p = step & 1;
        const float* inp0 = (step == 0) ? x : gx;

        float* h0_in  = hbuf + ((size_t)p       * LNUM + 0) * HDIM;
        float* h0_out = hbuf + ((size_t)(1 - p) * LNUM + 0) * HDIM;
        float* h1_in  = hbuf + ((size_t)p       * LNUM + 1) * HDIM;
        float* h1_out = hbuf + ((size_t)(1 - p) * LNUM + 1) * HDIM;

        lstm_gates_kernel<<<HDIM / 4, 512>>>(
            wih16, whh16, bih, bhh, inp0, h0_in, h0_out, cbuf);
        lstm_gates_kernel<<<HDIM / 4, 512>>>(
            wih16 + wOffL, whh16 + wOffL, bih + bOffL, bhh + bOffL,
            h0_out, h1_in, h1_out, cbuf + HDIM);
        logits_kernel<<<SDIM / 16, 512>>>(wout16, bout, h1_out, gl);
        softmax_kernel<<<1, 1024>>>(gl, out + (size_t)step * SDIM, gx);
    }
}

// round 3
// speedup vs baseline: 1.4915x; 1.2651x over previous
#include <cuda_runtime.h>
#include <cuda_fp16.h>
#include <math.h>

#define SDIM 2048
#define HDIM 2048
#define LNUM 2
#define ANUM 16
#define NLOGBLK 128   // logits kernel grid size (partial-sum count)

// Persistent scratch (__device__ globals only)
__device__ __align__(16) float g_hbuf[2][LNUM][HDIM];
__device__ __align__(16) float g_c[LNUM][HDIM];
__device__ __align__(16) float g_logits[SDIM];
__device__ __align__(16) float g_partial[NLOGBLK];
// fp16 weight caches, rebuilt every launch by the step-0 fused kernels
__device__ __align__(16) __half g_wih16[LNUM * 4 * HDIM * HDIM];
__device__ __align__(16) __half g_whh16[LNUM * 4 * HDIM * HDIM];
__device__ __align__(16) __half g_wout16[SDIM * HDIM];

__device__ __forceinline__ float sigmoidf_(float x) {
    return 1.0f / (1.0f + __expf(-x));
}

// ===========================================================================
// Shared helpers: smem staging into conflict-free split arrays.
// Vector of 2048 floats = 512 float4. Split: s0[p] = float4[2p], s1[p] = float4[2p+1].
// The dot-product inner loop then reads s0[lane+32k] / s1[lane+32k]:
// 16B-stride LDS.128, conflict-free.
// ===========================================================================

// ---------------------------------------------------------------------------
// LSTM gates, fp16 weights. MODE 0: inp is a plain [H] vector.
// MODE 1: inp is the previous step's logits; input = softmax computed inline
//         from partial exp-sums; block 0 also writes the normalized row to out_prev.
// Block = 512 thr = 16 warps = 4 units. Grid = HDIM/4 = 512.
// ---------------------------------------------------------------------------
template <int MODE>
__global__ void __launch_bounds__(512) lstm_gates_fp16(
    const __half* __restrict__ Wih, const __half* __restrict__ Whh,
    const float* __restrict__ bih, const float* __restrict__ bhh,
    const float* __restrict__ inp,        // [H] vector (MODE 0) or logits (MODE 1)
    const float* __restrict__ partials,   // [NLOGBLK] exp-sums (MODE 1)
    float* __restrict__ out_prev,         // output row for prev step (MODE 1)
    const float* __restrict__ hin,
    float* __restrict__ hout,
    float* __restrict__ cio)
{
    __shared__ float4 s_in0[256], s_in1[256], s_h0[256], s_h1[256];
    __shared__ float s_g[4][4];
    __shared__ float s_inv;

    const int t    = threadIdx.x;
    const int warp = t >> 5;
    const int lane = t & 31;

    if (MODE == 1) {
        if (warp == 0) {
            float s = 0.0f;
            #pragma unroll
            for (int j = 0; j < 4; j++) s += partials[lane + j * 32];
            #pragma unroll
            for (int o = 16; o > 0; o >>= 1)
                s += __shfl_xor_sync(0xffffffffu, s, o);
            if (lane == 0) s_inv = 1.0f / s;
        }
        __syncthreads();
    }

    // Stage input + hidden (one float4 per thread per vector)
    {
        float4 v;
        if (MODE == 1) {
            const float inv = s_inv;
            float4 lg = ((const float4*)inp)[t];
            v.x = __expf(lg.x) * inv;
            v.y = __expf(lg.y) * inv;
            v.z = __expf(lg.z) * inv;
            v.w = __expf(lg.w) * inv;
            if (blockIdx.x == 0) ((float4*)out_prev)[t] = v;
        } else {
            v = ((const float4*)inp)[t];
        }
        ((t & 1) ? s_in1 : s_in0)[t >> 1] = v;
        float4 hv = ((const float4*)hin)[t];
        ((t & 1) ? s_h1 : s_h0)[t >> 1] = hv;
    }
    __syncthreads();

    const int ulocal = warp >> 2;
    const int gate   = warp & 3;
    const int unit   = blockIdx.x * 4 + ulocal;
    const int row    = gate * HDIM + unit;

    const uint4* __restrict__ wi4 = (const uint4*)Wih + (size_t)row * (HDIM / 8);
    const uint4* __restrict__ wh4 = (const uint4*)Whh + (size_t)row * (HDIM / 8);

    float acc0 = 0.f, acc1 = 0.f, acc2 = 0.f, acc3 = 0.f;
    uint4 w[8];

    // ---- W_ih . inp ----
    #pragma unroll
    for (int k = 0; k < 8; k++) w[k] = wi4[lane + k * 32];
    #pragma unroll
    for (int k = 0; k < 8; k++) {
        const __half2* hp = reinterpret_cast<const __half2*>(&w[k]);
        float4 a0 = s_in0[lane + k * 32];
        float4 a1 = s_in1[lane + k * 32];
        float2 f0 = __half22float2(hp[0]);
        float2 f1 = __half22float2(hp[1]);
        float2 f2 = __half22float2(hp[2]);
        float2 f3 = __half22float2(hp[3]);
        acc0 = fmaf(f0.x, a0.x, acc0); acc1 = fmaf(f0.y, a0.y, acc1);
        acc2 = fmaf(f1.x, a0.z, acc2); acc3 = fmaf(f1.y, a0.w, acc3);
        acc0 = fmaf(f2.x, a1.x, acc0); acc1 = fmaf(f2.y, a1.y, acc1);
        acc2 = fmaf(f3.x, a1.z, acc2); acc3 = fmaf(f3.y, a1.w, acc3);
    }
    // ---- W_hh . h ----
    #pragma unroll
    for (int k = 0; k < 8; k++) w[k] = wh4[lane + k * 32];
    #pragma unroll
    for (int k = 0; k < 8; k++) {
        const __half2* hp = reinterpret_cast<const __half2*>(&w[k]);
        float4 a0 = s_h0[lane + k * 32];
        float4 a1 = s_h1[lane + k * 32];
        float2 f0 = __half22float2(hp[0]);
        float2 f1 = __half22float2(hp[1]);
        float2 f2 = __half22float2(hp[2]);
        float2 f3 = __half22float2(hp[3]);
        acc0 = fmaf(f0.x, a0.x, acc0); acc1 = fmaf(f0.y, a0.y, acc1);
        acc2 = fmaf(f1.x, a0.z, acc2); acc3 = fmaf(f1.y, a0.w, acc3);
        acc0 = fmaf(f2.x, a1.x, acc0); acc1 = fmaf(f2.y, a1.y, acc1);
        acc2 = fmaf(f3.x, a1.z, acc2); acc3 = fmaf(f3.y, a1.w, acc3);
    }

    float acc = (acc0 + acc1) + (acc2 + acc3);
    #pragma unroll
    for (int o = 16; o > 0; o >>= 1)
        acc += __shfl_xor_sync(0xffffffffu, acc, o);
    if (lane == 0)
        s_g[ulocal][gate] = acc + bih[row] + bhh[row];
    __syncthreads();

    if (t < 4) {
        const int u = blockIdx.x * 4 + t;
        float iv = sigmoidf_(s_g[t][0]);
        float fv = sigmoidf_(s_g[t][1]);
        float gv = tanhf(s_g[t][2]);
        float ov = sigmoidf_(s_g[t][3]);
        float cn = fv * cio[u] + iv * gv;
        cio[u]  = cn;
        hout[u] = ov * tanhf(cn);
    }
}

// ---------------------------------------------------------------------------
// Step-0 fused: compute gates from fp32 weights AND write the fp16 cache.
// ---------------------------------------------------------------------------
__global__ void __launch_bounds__(512) lstm_gates_cvt(
    const float* __restrict__ Wih32, const float* __restrict__ Whh32,
    __half* __restrict__ WihC, __half* __restrict__ WhhC,
    const float* __restrict__ bih, const float* __restrict__ bhh,
    const float* __restrict__ inp,
    const float* __restrict__ hin,
    float* __restrict__ hout,
    float* __restrict__ cio)
{
    __shared__ float4 s_in0[256], s_in1[256], s_h0[256], s_h1[256];
    __shared__ float s_g[4][4];

    const int t    = threadIdx.x;
    const int warp = t >> 5;
    const int lane = t & 31;

    {
        float4 v = ((const float4*)inp)[t];
        ((t & 1) ? s_in1 : s_in0)[t >> 1] = v;
        float4 hv = ((const float4*)hin)[t];
        ((t & 1) ? s_h1 : s_h0)[t >> 1] = hv;
    }
    __syncthreads();

    const int ulocal = warp >> 2;
    const int gate   = warp & 3;
    const int unit   = blockIdx.x * 4 + ulocal;
    const int row    = gate * HDIM + unit;

    const float4* __restrict__ wi32 = (const float4*)Wih32 + (size_t)row * (HDIM / 4);
    const float4* __restrict__ wh32 = (const float4*)Whh32 + (size_t)row * (HDIM / 4);
    uint2* __restrict__ wiC = (uint2*)(WihC + (size_t)row * HDIM);
    uint2* __restrict__ whC = (uint2*)(WhhC + (size_t)row * HDIM);

    float acc0 = 0.f, acc1 = 0.f, acc2 = 0.f, acc3 = 0.f;
    const float4* sel_in = (lane & 1) ? s_in1 : s_in0;
    const float4* sel_h  = (lane & 1) ? s_h1  : s_h0;

    #pragma unroll
    for (int j = 0; j < 16; j += 4) {
        float4 wv[4];
        #pragma unroll
        for (int jj = 0; jj < 4; jj++) wv[jj] = wi32[lane + (j + jj) * 32];
        #pragma unroll
        for (int jj = 0; jj < 4; jj++) {
            const int f = lane + (j + jj) * 32;
            __half2 p0 = __floats2half2_rn(wv[jj].x, wv[jj].y);
            __half2 p1 = __floats2half2_rn(wv[jj].z, wv[jj].w);
            uint2 st; st.x = *(unsigned*)&p0; st.y = *(unsigned*)&p1;
            wiC[f] = st;
            float4 a = sel_in[f >> 1];
            acc0 = fmaf(wv[jj].x, a.x, acc0); acc1 = fmaf(wv[jj].y, a.y, acc1);
            acc2 = fmaf(wv[jj].z, a.z, acc2); acc3 = fmaf(wv[jj].w, a.w, acc3);
        }
    }
    #pragma unroll
    for (int j = 0; j < 16; j += 4) {
        float4 wv[4];
        #pragma unroll
        for (int jj = 0; jj < 4; jj++) wv[jj] = wh32[lane + (j + jj) * 32];
        #pragma unroll
        for (int jj = 0; jj < 4; jj++) {
            const int f = lane + (j + jj) * 32;
            __half2 p0 = __floats2half2_rn(wv[jj].x, wv[jj].y);
            __half2 p1 = __floats2half2_rn(wv[jj].z, wv[jj].w);
            uint2 st; st.x = *(unsigned*)&p0; st.y = *(unsigned*)&p1;
            whC[f] = st;
            float4 a = sel_h[f >> 1];
            acc0 = fmaf(wv[jj].x, a.x, acc0); acc1 = fmaf(wv[jj].y, a.y, acc1);
            acc2 = fmaf(wv[jj].z, a.z, acc2); acc3 = fmaf(wv[jj].w, a.w, acc3);
        }
    }

    float acc = (acc0 + acc1) + (acc2 + acc3);
    #pragma unroll
    for (int o = 16; o > 0; o >>= 1)
        acc += __shfl_xor_sync(0xffffffffu, acc, o);
    if (lane == 0)
        s_g[ulocal][gate] = acc + bih[row] + bhh[row];
    __syncthreads();

    if (t < 4) {
        const int u = blockIdx.x * 4 + t;
        float iv = sigmoidf_(s_g[t][0]);
        float fv = sigmoidf_(s_g[t][1]);
        float gv = tanhf(s_g[t][2]);
        float ov = sigmoidf_(s_g[t][3]);
        float cn = fv * cio[u] + iv * gv;
        cio[u]  = cn;
        hout[u] = ov * tanhf(cn);
    }
}

// ---------------------------------------------------------------------------
// Logits (fp16 weights) + deterministic per-block exp-sum partials.
// Block = 512 thr = 16 rows. Grid = NLOGBLK = 128.
// ---------------------------------------------------------------------------
__global__ void __launch_bounds__(512) logits_fp16(
    const __half* __restrict__ Wout,
    const float* __restrict__ bout,
    const float* __restrict__ h,
    float* __restrict__ logits,
    float* __restrict__ partials)
{
    __shared__ float4 s_h0[256], s_h1[256];
    __shared__ float s_e[16];

    const int t    = threadIdx.x;
    const int warp = t >> 5;
    const int lane = t & 31;

    {
        float4 hv = ((const float4*)h)[t];
        ((t & 1) ? s_h1 : s_h0)[t >> 1] = hv;
    }
    __syncthreads();

    const int row = blockIdx.x * 16 + warp;
    const uint4* __restrict__ w4 = (const uint4*)Wout + (size_t)row * (HDIM / 8);

    float acc0 = 0.f, acc1 = 0.f, acc2 = 0.f, acc3 = 0.f;
    uint4 w[8];
    #pragma unroll
    for (int k = 0; k < 8; k++) w[k] = w4[lane + k * 32];
    #pragma unroll
    for (int k = 0; k < 8; k++) {
        const __half2* hp = reinterpret_cast<const __half2*>(&w[k]);
        float4 a0 = s_h0[lane + k * 32];
        float4 a1 = s_h1[lane + k * 32];
        float2 f0 = __half22float2(hp[0]);
        float2 f1 = __half22float2(hp[1]);
        float2 f2 = __half22float2(hp[2]);
        float2 f3 = __half22float2(hp[3]);
        acc0 = fmaf(f0.x, a0.x, acc0); acc1 = fmaf(f0.y, a0.y, acc1);
        acc2 = fmaf(f1.x, a0.z, acc2); acc3 = fmaf(f1.y, a0.w, acc3);
        acc0 = fmaf(f2.x, a1.x, acc0); acc1 = fmaf(f2.y, a1.y, acc1);
        acc2 = fmaf(f3.x, a1.z, acc2); acc3 = fmaf(f3.y, a1.w, acc3);
    }

    float acc = (acc0 + acc1) + (acc2 + acc3);
    #pragma unroll
    for (int o = 16; o > 0; o >>= 1)
        acc += __shfl_xor_sync(0xffffffffu, acc, o);
    if (lane == 0) {
        float lg = acc + bout[row];
        logits[row] = lg;
        s_e[warp] = __expf(lg);
    }
    __syncthreads();
    if (warp == 0) {
        float v = (lane < 16) ? s_e[lane] : 0.0f;
        #pragma unroll
        for (int o = 16; o > 0; o >>= 1)
            v += __shfl_xor_sync(0xffffffffu, v, o);
        if (lane == 0) partials[blockIdx.x] = v;
    }
}

// Step-0 fused logits: fp32 weights + write fp16 cache.
__global__ void __launch_bounds__(512) logits_cvt(
    const float* __restrict__ Wout32,
    __half* __restrict__ WoutC,
    const float* __restrict__ bout,
    const float* __restrict__ h,
    float* __restrict__ logits,
    float* __restrict__ partials)
{
    __shared__ float4 s_h0[256], s_h1[256];
    __shared__ float s_e[16];

    const int t    = threadIdx.x;
    const int warp = t >> 5;
    const int lane = t & 31;

    {
        float4 hv = ((const float4*)h)[t];
        ((t & 1) ? s_h1 : s_h0)[t >> 1] = hv;
    }
    __syncthreads();

    const int row = blockIdx.x * 16 + warp;
    const float4* __restrict__ w32 = (const float4*)Wout32 + (size_t)row * (HDIM / 4);
    uint2* __restrict__ wC = (uint2*)(WoutC + (size_t)row * HDIM);
    const float4* sel_h = (lane & 1) ? s_h1 : s_h0;

    float acc0 = 0.f, acc1 = 0.f, acc2 = 0.f, acc3 = 0.f;
    #pragma unroll
    for (int j = 0; j < 16; j += 4) {
        float4 wv[4];
        #pragma unroll
        for (int jj = 0; jj < 4; jj++) wv[jj] = w32[lane + (j + jj) * 32];
        #pragma unroll
        for (int jj = 0; jj < 4; jj++) {
            const int f = lane + (j + jj) * 32;
            __half2 p0 = __floats2half2_rn(wv[jj].x, wv[jj].y);
            __half2 p1 = __floats2half2_rn(wv[jj].z, wv[jj].w);
            uint2 st; st.x = *(unsigned*)&p0; st.y = *(unsigned*)&p1;
            wC[f] = st;
            float4 a = sel_h[f >> 1];
            acc0 = fmaf(wv[jj].x, a.x, acc0); acc1 = fmaf(wv[jj].y, a.y, acc1);
            acc2 = fmaf(wv[jj].z, a.z, acc2); acc3 = fmaf(wv[jj].w, a.w, acc3);
        }
    }

    float acc = (acc0 + acc1) + (acc2 + acc3);
    #pragma unroll
    for (int o = 16; o > 0; o >>= 1)
        acc += __shfl_xor_sync(0xffffffffu, acc, o);
    if (lane == 0) {
        float lg = acc + bout[row];
        logits[row] = lg;
        s_e[warp] = __expf(lg);
    }
    __syncthreads();
    if (warp == 0) {
        float v = (lane < 16) ? s_e[lane] : 0.0f;
        #pragma unroll
        for (int o = 16; o > 0; o >>= 1)
            v += __shfl_xor_sync(0xffffffffu, v, o);
        if (lane == 0) partials[blockIdx.x] = v;
    }
}

// Final step's softmax output (step ANUM-1).
__global__ void __launch_bounds__(512) final_softmax_kernel(
    const float* __restrict__ logits,
    const float* __restrict__ partials,
    float* __restrict__ out_row)
{
    __shared__ float s_inv;
    const int t    = threadIdx.x;
    const int warp = t >> 5;
    const int lane = t & 31;
    if (warp == 0) {
        float s = 0.0f;
        #pragma unroll
        for (int j = 0; j < 4; j++) s += partials[lane + j * 32];
        #pragma unroll
        for (int o = 16; o > 0; o >>= 1)
            s += __shfl_xor_sync(0xffffffffu, s, o);
        if (lane == 0) s_inv = 1.0f / s;
    }
    __syncthreads();
    const float inv = s_inv;
    float4 lg = ((const float4*)logits)[t];
    float4 v;
    v.x = __expf(lg.x) * inv;
    v.y = __expf(lg.y) * inv;
    v.z = __expf(lg.z) * inv;
    v.w = __expf(lg.w) * inv;
    ((float4*)out_row)[t] = v;
}

// ---------------------------------------------------------------------------
extern "C" void kernel_launch(void* const* d_in, const int* in_sizes, int n_in,
                              void* d_out, int out_size)
{
    const float* x    = (const float*)d_in[0];
    const float* Wih  = (const float*)d_in[1];
    const float* Whh  = (const float*)d_in[2];
    const float* bih  = (const float*)d_in[3];
    const float* bhh  = (const float*)d_in[4];
    const float* Wout = (const float*)d_in[5];
    const float* bout = (const float*)d_in[6];
    float* out = (float*)d_out;

    float *hbuf, *cbuf, *gl, *gp;
    __half *wih16, *whh16, *wout16;
    cudaGetSymbolAddress((void**)&hbuf,   g_hbuf);
    cudaGetSymbolAddress((void**)&cbuf,   g_c);
    cudaGetSymbolAddress((void**)&gl,     g_logits);
    cudaGetSymbolAddress((void**)&gp,     g_partial);
    cudaGetSymbolAddress((void**)&wih16,  g_wih16);
    cudaGetSymbolAddress((void**)&whh16,  g_whh16);
    cudaGetSymbolAddress((void**)&wout16, g_wout16);

    cudaMemsetAsync(hbuf, 0, sizeof(float) * 2 * LNUM * HDIM);
    cudaMemsetAsync(cbuf, 0, sizeof(float) * LNUM * HDIM);

    const size_t wOffL = (size_t)4 * HDIM * HDIM;
    const size_t bOffL = (size_t)4 * HDIM;

    // ---- step 0: fused compute + fp16 conversion ----
    {
        float* h0_in  = hbuf + 0 * LNUM * HDIM;
        float* h0_out = hbuf + 1 * LNUM * HDIM;
        float* h1_in  = hbuf + (0 * LNUM + 1) * HDIM;
        float* h1_out = hbuf + (1 * LNUM + 1) * HDIM;

        lstm_gates_cvt<<<HDIM / 4, 512>>>(
            Wih, Whh, wih16, whh16, bih, bhh, x, h0_in, h0_out, cbuf);
        lstm_gates_cvt<<<HDIM / 4, 512>>>(
            Wih + wOffL, Whh + wOffL, wih16 + wOffL, whh16 + wOffL,
            bih + bOffL, bhh + bOffL, h0_out, h1_in, h1_out, cbuf + HDIM);
        logits_cvt<<<NLOGBLK, 512>>>(Wout, wout16, bout, h1_out, gl, gp);
    }

    // ---- steps 1..A-1: fp16 weights, softmax fused into layer-0 staging ----
    for (int step = 1; step < ANUM; step++) {
        const int p = step & 1;
        float* h0_in  = hbuf + ((size_t)p       * LNUM + 0) * HDIM;
        float* h0_out = hbuf + ((size_t)(1 - p) * LNUM + 0) * HDIM;
        float* h1_in  = hbuf + ((size_t)p       * LNUM + 1) * HDIM;
        float* h1_out = hbuf + ((size_t)(1 - p) * LNUM + 1) * HDIM;

        lstm_gates_fp16<1><<<HDIM / 4, 512>>>(
            wih16, whh16, bih, bhh,
            gl, gp, out + (size_t)(step - 1) * SDIM,
            h0_in, h0_out, cbuf);
        lstm_gates_fp16<0><<<HDIM / 4, 512>>>(
            wih16 + wOffL, whh16 + wOffL, bih + bOffL, bhh + bOffL,
            h0_out, nullptr, nullptr,
            h1_in, h1_out, cbuf + HDIM);
        logits_fp16<<<NLOGBLK, 512>>>(wout16, bout, h1_out, gl, gp);
    }

    // ---- final softmax output row ----
    final_softmax_kernel<<<1, 512>>>(gl, gp, out + (size_t)(ANUM - 1) * SDIM);
}